// round 17
// baseline (speedup 1.0000x reference)
#include <cuda_runtime.h>
#include <cuda_bf16.h>
#include <cuda_fp16.h>
#include <cstdint>

#define B_ 16
#define C_ 512
#define N_ 4096
#define M_ 2048

// ---------------- device scratch: tile-contiguous, SW128-pre-swizzled ----------------
// Q hi/lo: [ttile(512)][kc(8)][16384B]  (128 tokens x 128B, swizzled)
__device__ __align__(128) char g_qh2[67108864];
__device__ __align__(128) char g_ql2[67108864];
// Mem hi/lo: [subtile(16)][kc(8)][16384B]  (128 mrows x 128B, swizzled)
__device__ __align__(128) char g_mh2[2097152];
__device__ __align__(128) char g_ml2[2097152];
// MemT fp16 (gemm2 B): [kc(32)][nt(2)][32768B]  (256 C-rows x 128B, swizzled)
__device__ __align__(128) char g_mtf2[2097152];
__device__ float g_S[134217728];   // [B*N, M] raw scores (512 MB)
__device__ float g_rowmax[65536];  // [B*N]

// ---------------- arch feature gate (tcgen05 only; bulk/mapa/cluster are sm90-base) ----------------
#if defined(__CUDA_ARCH_FEAT_SM103_ALL) || defined(__CUDA_ARCH_FEAT_SM100_ALL) || defined(__CUDA_ARCH_FEAT_SM101_ALL)
#define TC_OK 1
#else
#define TC_OK 0
#endif

typedef unsigned long long ull;

__device__ __forceinline__ uint32_t smem_u32(const void* p) {
    uint32_t a;
    asm("{ .reg .u64 t; cvta.to.shared.u64 t, %1; cvt.u32.u64 %0, t; }" : "=r"(a) : "l"(p));
    return a;
}

#if TC_OK
#define TCALLOC(sm, n)      asm volatile("tcgen05.alloc.cta_group::1.sync.aligned.shared::cta.b32 [%0], %1;" :: "r"(sm), "r"(n) : "memory")
#define TCDEALLOC(t, n)     asm volatile("tcgen05.dealloc.cta_group::1.sync.aligned.b32 %0, %1;" :: "r"(t), "r"(n))
#define TCALLOC_CG2(sm, n)  asm volatile("tcgen05.alloc.cta_group::2.sync.aligned.shared::cta.b32 [%0], %1;" :: "r"(sm), "r"(n) : "memory")
#define TCDEALLOC_CG2(t, n) asm volatile("tcgen05.dealloc.cta_group::2.sync.aligned.b32 %0, %1;" :: "r"(t), "r"(n))
#define TCRELINQ_CG2()      asm volatile("tcgen05.relinquish_alloc_permit.cta_group::2.sync.aligned;")
#define TCCOMMIT(mb)        asm volatile("tcgen05.commit.cta_group::1.mbarrier::arrive::one.shared::cluster.b64 [%0];" :: "r"(mb) : "memory")
#define TCCOMMIT_MC2(mb, mask) asm volatile("tcgen05.commit.cta_group::2.mbarrier::arrive::one.shared::cluster.multicast::cluster.b64 [%0], %1;" :: "r"(mb), "h"((uint16_t)(mask)) : "memory")
#define TCFENCE_AFTER()     asm volatile("tcgen05.fence::after_thread_sync;" ::: "memory")
#define TCWAIT_LD()         asm volatile("tcgen05.wait::ld.sync.aligned;" ::: "memory")
#else
#define TCALLOC(sm, n)      ((void)0)
#define TCDEALLOC(t, n)     ((void)0)
#define TCALLOC_CG2(sm, n)  ((void)0)
#define TCDEALLOC_CG2(t, n) ((void)0)
#define TCRELINQ_CG2()      ((void)0)
#define TCCOMMIT(mb)        ((void)0)
#define TCCOMMIT_MC2(mb, mask) ((void)0)
#define TCFENCE_AFTER()     ((void)0)
#define TCWAIT_LD()         ((void)0)
#endif

#define MBINIT(mb, c)   asm volatile("mbarrier.init.shared.b64 [%0], %1;" :: "r"(mb), "r"(c) : "memory")
#define MBEXPECT(mb, n) asm volatile("mbarrier.arrive.expect_tx.shared.b64 _, [%0], %1;" :: "r"(mb), "r"(n) : "memory")
#define FENCE_ASYNC()   asm volatile("fence.proxy.async.shared::cta;" ::: "memory")
#define CLUSTER_SYNC()  do { asm volatile("barrier.cluster.arrive.aligned;" ::: "memory"); \
                             asm volatile("barrier.cluster.wait.aligned;" ::: "memory"); } while (0)

__device__ __forceinline__ uint32_t cluster_rank() {
    uint32_t r;
    asm("mov.u32 %0, %%cluster_ctarank;" : "=r"(r));
    return r;
}
// arrive on the mbarrier at the same SMEM offset in cluster CTA `target`
__device__ __forceinline__ void mbar_arrive_rank(uint32_t local_mbar, uint32_t target) {
    asm volatile("{\n\t.reg .b32 ra;\n\t"
        "mapa.shared::cluster.u32 ra, %0, %1;\n\t"
        "mbarrier.arrive.shared::cluster.b64 _, [ra];\n\t}"
        :: "r"(local_mbar), "r"(target) : "memory");
}

#define MBWAIT(mb, par) do {                                                       \
    uint32_t _m = (mb), _p = (par), _d;                                            \
    asm volatile("{\n\t.reg .pred p;\n\t"                                          \
        "mbarrier.try_wait.parity.acquire.cta.shared::cta.b64 p, [%1], %2;\n\t"    \
        "selp.b32 %0, 1, 0, p;\n\t}" : "=r"(_d) : "r"(_m), "r"(_p) : "memory");    \
    if (!_d) {                                                                     \
        asm volatile("{\n\t.reg .pred P1;\n\t"                                     \
            "WL_%=:\n\t"                                                           \
            "mbarrier.try_wait.parity.acquire.cta.shared::cta.b64 P1, [%0], %1, 0x989680;\n\t" \
            "@P1 bra.uni WD_%=;\n\t"                                               \
            "bra.uni WL_%=;\n\t"                                                   \
            "WD_%=:\n\t}" :: "r"(_m), "r"(_p) : "memory");                         \
    }                                                                              \
} while (0)

// bulk copy gmem -> smem
__device__ __forceinline__ void bulk_g2s(uint32_t dst, const void* src, uint32_t bytes, uint32_t mbar) {
    asm volatile("cp.async.bulk.shared::cluster.global.mbarrier::complete_tx::bytes [%0], [%1], %2, [%3];"
        :: "r"(dst), "l"(src), "r"(bytes), "r"(mbar) : "memory");
}

#if TC_OK
#define LDTM_X32(r, addr) \
    asm volatile("tcgen05.ld.sync.aligned.32x32b.x32.b32 " \
        "{%0,%1,%2,%3,%4,%5,%6,%7,%8,%9,%10,%11,%12,%13,%14,%15," \
        "%16,%17,%18,%19,%20,%21,%22,%23,%24,%25,%26,%27,%28,%29,%30,%31}, [%32];" \
        : "=r"((r)[0]),"=r"((r)[1]),"=r"((r)[2]),"=r"((r)[3]),"=r"((r)[4]),"=r"((r)[5]),"=r"((r)[6]),"=r"((r)[7]), \
          "=r"((r)[8]),"=r"((r)[9]),"=r"((r)[10]),"=r"((r)[11]),"=r"((r)[12]),"=r"((r)[13]),"=r"((r)[14]),"=r"((r)[15]), \
          "=r"((r)[16]),"=r"((r)[17]),"=r"((r)[18]),"=r"((r)[19]),"=r"((r)[20]),"=r"((r)[21]),"=r"((r)[22]),"=r"((r)[23]), \
          "=r"((r)[24]),"=r"((r)[25]),"=r"((r)[26]),"=r"((r)[27]),"=r"((r)[28]),"=r"((r)[29]),"=r"((r)[30]),"=r"((r)[31]) \
        : "r"(addr))
#else
#define LDTM_X32(r, addr) do { _Pragma("unroll") for (int _z = 0; _z < 32; _z++) (r)[_z] = 0u; (void)(addr); } while (0)
#endif

__device__ __forceinline__ void mma_f16_ss(uint32_t d, uint64_t a, uint64_t b,
                                           uint32_t idesc, uint32_t en) {
#if TC_OK
    asm volatile("{\n\t.reg .pred p;\n\tsetp.ne.u32 p, %4, 0;\n\t"
        "tcgen05.mma.cta_group::1.kind::f16 [%0], %1, %2, %3, {%5,%5,%5,%5}, p;\n\t}"
        :: "r"(d), "l"(a), "l"(b), "r"(idesc), "r"(en), "r"(0u) : "memory");
#else
    (void)d; (void)a; (void)b; (void)idesc; (void)en;
#endif
}
__device__ __forceinline__ void mma_f16_ss_cg2(uint32_t d, uint64_t a, uint64_t b,
                                               uint32_t idesc, uint32_t en) {
#if TC_OK
    asm volatile("{\n\t.reg .pred p;\n\tsetp.ne.u32 p, %5, 0;\n\t"
        "tcgen05.mma.cta_group::2.kind::f16 [%0], %1, %2, %3, {%4,%4,%4,%4,%4,%4,%4,%4}, p;\n\t}"
        :: "r"(d), "l"(a), "l"(b), "r"(idesc), "r"(0u), "r"(en) : "memory");
#else
    (void)d; (void)a; (void)b; (void)idesc; (void)en;
#endif
}

// SW128 swizzle + descriptor
#define SW128(o) ((uint32_t)(o) ^ ((((uint32_t)(o)) >> 3) & 0x70u))
static __device__ __forceinline__ uint64_t mk_desc(uint32_t addr) {
    const uint64_t base = (uint64_t(2) << 61) | (uint64_t(1) << 46)
                        | (uint64_t(64) << 32) | (uint64_t(1) << 16);
    return base | ((uint64_t)(addr >> 4) & 0x3FFF);
}

#define IDESC_BF16_CG2 ((1u<<4) | (1u<<7) | (1u<<10) | ((256u/8)<<17) | ((256u/16)<<24))
#define IDESC_F16      ((1u<<4) |                     ((256u/8)<<17) | ((128u/16)<<24))

__device__ __forceinline__ void atomicMaxFloat(float* addr, float v) {
    if (v >= 0.0f) atomicMax((int*)addr, __float_as_int(v));
    else           atomicMin((unsigned int*)addr, __float_as_uint(v));
}

// ================= K0: init rowmax =================
__global__ void k_init_rowmax() {
    g_rowmax[blockIdx.x * 256 + threadIdx.x] = -3.0e38f;
}

// ================= K1a: features -> pre-swizzled Q hi/lo tiles =================
__global__ void k_prep_feat(const float* __restrict__ feat) {
    __shared__ float tile[32][33];
    int c0 = blockIdx.x * 32, n0 = blockIdx.y * 32, b = blockIdx.z;
    int tx = threadIdx.x & 31, ty = threadIdx.x >> 5;
    const float* fb = feat + ((size_t)b * C_ + c0) * N_ + n0;
    #pragma unroll
    for (int i = ty; i < 32; i += 8)
        tile[i][tx] = fb[(size_t)i * N_ + tx];
    __syncthreads();
    int t = threadIdx.x;
    int cp = t & 15;
    int nl = t >> 4;
    #pragma unroll
    for (int k = 0; k < 2; k++) {
        int n = nl + 16 * k;
        float x0 = tile[2 * cp][n], x1 = tile[2 * cp + 1][n];
        __nv_bfloat16 h0 = __float2bfloat16(x0);
        __nv_bfloat16 h1 = __float2bfloat16(x1);
        __nv_bfloat16 l0 = __float2bfloat16(x0 - __bfloat162float(h0));
        __nv_bfloat16 l1 = __float2bfloat16(x1 - __bfloat162float(h1));
        int tokg = b * N_ + n0 + n;
        int tt = tokg >> 7, rowloc = tokg & 127;
        int c = c0 + 2 * cp;
        int kc = c >> 6;
        uint32_t boff = (uint32_t)(c & 63) * 2;
        size_t dst = (size_t)(tt * 8 + kc) * 16384 + SW128(rowloc * 128 + boff);
        *(__nv_bfloat162*)(g_qh2 + dst) = __nv_bfloat162(h0, h1);
        *(__nv_bfloat162*)(g_ql2 + dst) = __nv_bfloat162(l0, l1);
    }
}

// ================= K1b: mem -> pre-swizzled hi/lo 128-row subtiles =================
__global__ void k_prep_mem(const float* __restrict__ mem) {
    int i = blockIdx.x * blockDim.x + threadIdx.x;   // pair index
    if (i >= M_ * C_ / 2) return;
    float2 v = ((const float2*)mem)[i];
    __nv_bfloat16 h0 = __float2bfloat16(v.x);
    __nv_bfloat16 h1 = __float2bfloat16(v.y);
    __nv_bfloat16 l0 = __float2bfloat16(v.x - __bfloat162float(h0));
    __nv_bfloat16 l1 = __float2bfloat16(v.y - __bfloat162float(h1));
    int m = i >> 8;
    int c = (i & 255) * 2;
    int st = m >> 7, rowloc = m & 127;     // 16 subtiles of 128 mrows
    int kc = c >> 6;
    uint32_t boff = (uint32_t)(c & 63) * 2;
    size_t dst = (size_t)(st * 8 + kc) * 16384 + SW128(rowloc * 128 + boff);
    *(__nv_bfloat162*)(g_mh2 + dst) = __nv_bfloat162(h0, h1);
    *(__nv_bfloat162*)(g_ml2 + dst) = __nv_bfloat162(l0, l1);
}

// ================= K1c: memT fp16 -> pre-swizzled gemm2 B tiles =================
__global__ void k_prep_memT(const float* __restrict__ mem) {
    __shared__ float tile[32][33];
    int m0 = blockIdx.x * 32, c0 = blockIdx.y * 32;
    int tx = threadIdx.x & 31, ty = threadIdx.x >> 5;
    #pragma unroll
    for (int i = ty; i < 32; i += 8)
        tile[i][tx] = mem[(size_t)(m0 + i) * C_ + c0 + tx];
    __syncthreads();
    int t = threadIdx.x;
    if (t < 128) {
        int i = t >> 2;
        int j = t & 3;
        int c = c0 + i;
        int nt = c >> 8, rowloc = c & 255;
        int kc = m0 >> 6;
        int mb = (m0 & 63) + j * 8;
        __half h[8];
        #pragma unroll
        for (int k = 0; k < 8; k++) h[k] = __float2half(tile[j * 8 + k][i]);
        size_t dst = (size_t)(kc * 2 + nt) * 32768 + SW128(rowloc * 128 + mb * 2);
        *(uint4*)(g_mtf2 + dst) = *(uint4*)h;
    }
}

// ================= K2: GEMM1 cg2 (split-bf16, M=256 pair, B split N/2) =================
// grid: (512 ttiles, 8 mtiles), cluster (2,1,1) on x; 256 threads
// smem: header 1024 | stage s: AH16K AL16K BH16K BL16K (=65536) x2 ; epilogue St overlaps
#define G1_STAGE 65536
#define G1_BASE(s) (1024u + (uint32_t)(s) * G1_STAGE)
#define G1_SMEM 134144   // >= 1024 + 2*65536 and >= 1024 + 128*260*4 (epilogue staging)

__global__ __launch_bounds__(256, 1) __cluster_dims__(2, 1, 1)
void k_gemm1() {
    extern __shared__ char smem[];
    uint32_t sb = smem_u32(smem);
    int t = threadIdx.x, wid = t >> 5, lane = t & 31;
    int ttile = blockIdx.x;          // 0..511 (pairs: even=rank0, odd=rank1)
    int mtile = blockIdx.y;          // 0..7
    uint32_t rank = cluster_rank();

    if (wid == 0) TCALLOC_CG2(sb, 512);
    if (t == 0) {
        MBINIT(sb + 16, 1); MBINIT(sb + 24, 1);   // full[0..1]  (own bulk tx)
        MBINIT(sb + 32, 1); MBINIT(sb + 40, 1);   // empty[0..1] (MMA commit, multicast)
        MBINIT(sb + 48, 1); MBINIT(sb + 56, 1);   // ready[0..1] (rank1 -> rank0)
    }
    __syncthreads();
    CLUSTER_SYNC();   // barriers visible cluster-wide before remote arrivals/commits

    uint32_t tmem;
    asm volatile("ld.shared.b32 %0, [%1];" : "=r"(tmem) : "r"(sb));

    const char* qh = g_qh2 + (size_t)ttile * (8 * 16384);
    const char* ql = g_ql2 + (size_t)ttile * (8 * 16384);
    const int  sub = mtile * 2 + (int)rank;                 // this CTA's B half
    const char* mh = g_mh2 + (size_t)sub * (8 * 16384);
    const char* ml = g_ml2 + (size_t)sub * (8 * 16384);

    if (t == 0) {
        auto load_stage = [&](int s, int kc) {
            uint32_t full = sb + 16 + 8 * s, base = sb + G1_BASE(s);
            MBEXPECT(full, 65536u);
            bulk_g2s(base,         qh + (size_t)kc * 16384, 16384u, full);
            bulk_g2s(base + 16384, ql + (size_t)kc * 16384, 16384u, full);
            bulk_g2s(base + 32768, mh + (size_t)kc * 16384, 16384u, full);
            bulk_g2s(base + 49152, ml + (size_t)kc * 16384, 16384u, full);
        };
        load_stage(0, 0);
        load_stage(1, 1);
        for (int kc = 0; kc < 8; kc++) {
            int s = kc & 1;
            uint32_t par = (uint32_t)((kc >> 1) & 1);
            MBWAIT(sb + 16 + 8 * s, par);              // own stage full
            if (rank != 0) {
                mbar_arrive_rank(sb + 48 + 8 * s, 0);  // signal leader
            } else {
                MBWAIT(sb + 48 + 8 * s, par);          // peer stage full
                uint32_t base = G1_BASE(s);
                uint64_t ah = mk_desc(sb + base),         al = mk_desc(sb + base + 16384);
                uint64_t bh = mk_desc(sb + base + 32768), bl = mk_desc(sb + base + 49152);
                #pragma unroll
                for (int ks = 0; ks < 4; ks++)
                    mma_f16_ss_cg2(tmem, ah + 2 * ks, bh + 2 * ks, IDESC_BF16_CG2,
                                   (kc == 0 && ks == 0) ? 0u : 1u);
                #pragma unroll
                for (int ks = 0; ks < 4; ks++)
                    mma_f16_ss_cg2(tmem, ah + 2 * ks, bl + 2 * ks, IDESC_BF16_CG2, 1u);
                #pragma unroll
                for (int ks = 0; ks < 4; ks++)
                    mma_f16_ss_cg2(tmem, al + 2 * ks, bh + 2 * ks, IDESC_BF16_CG2, 1u);
                TCCOMMIT_MC2(sb + 32 + 8 * s, 0x3);    // empty[s] on both CTAs
            }
            if (kc + 2 < 8) {
                MBWAIT(sb + 32 + 8 * s, par);          // MMA kc done (both ranks)
                load_stage(s, kc + 2);
            }
        }
        // drain: 4th commit per stage -> parity 1
        MBWAIT(sb + 32, 1);
        MBWAIT(sb + 40, 1);
    }
    __syncthreads();
    TCFENCE_AFTER();

    // epilogue: each CTA reads its own TMEM D[128x256] -> staging -> g_S ; fused row max
    float* St = (float*)(smem + 1024);
    if (wid < 4) {
        int tok = wid * 32 + lane;
        float mx = -3.0e38f;
        #pragma unroll 1
        for (int cc = 0; cc < 8; cc++) {
            uint32_t r[32];
            LDTM_X32(r, tmem + cc * 32);
            TCWAIT_LD();
            #pragma unroll
            for (int u = 0; u < 8; u++) {
                float4 v = make_float4(__uint_as_float(r[4*u]),   __uint_as_float(r[4*u+1]),
                                       __uint_as_float(r[4*u+2]), __uint_as_float(r[4*u+3]));
                mx = fmaxf(mx, fmaxf(fmaxf(v.x, v.y), fmaxf(v.z, v.w)));
                *(float4*)(St + tok * 260 + cc * 32 + 4 * u) = v;
            }
        }
        atomicMaxFloat(&g_rowmax[ttile * 128 + tok], mx);
    }
    __syncthreads();
    {
        int tok = t >> 1, half = t & 1;
        const float4* src = (const float4*)(St + tok * 260 + half * 128);
        float4* dst = (float4*)(g_S + ((size_t)ttile * 128 + tok) * 2048
                                    + mtile * 256 + half * 128);
        #pragma unroll
        for (int i = 0; i < 32; i++) dst[i] = src[i];
    }
    __syncthreads();
    if (wid == 0) { TCRELINQ_CG2(); TCDEALLOC_CG2(tmem, 512); }
    CLUSTER_SYNC();
}

// ================= K4: softmax-convert + fp16 GEMM2 (bulk B, 2-stage) =================
#define G2_STAGE 81920
#define G2_BASE(s) (1024u + (uint32_t)(s) * G2_STAGE)
#define G2_SMEM (1024 + 2 * G2_STAGE)

__global__ __launch_bounds__(512, 1)
void k_gemm2(float* __restrict__ out) {
    extern __shared__ char smem[];
    uint32_t sb = smem_u32(smem);
    float* l_s = (float*)(smem + 64);
    int t = threadIdx.x, wid = t >> 5, lane = t & 31;
    int tile = blockIdx.x;
    int b = tile >> 5, n0 = (tile & 31) * 128;

    if (wid == 0) TCALLOC(sb, 512);
    if (t == 0) {
        MBINIT(sb + 16, 1); MBINIT(sb + 24, 1);
        MBINIT(sb + 32, 1); MBINIT(sb + 40, 1);
    }
    __syncthreads();
    uint32_t tmem;
    asm volatile("ld.shared.b32 %0, [%1];" : "=r"(tmem) : "r"(sb));

    const int tok = t >> 2, q = t & 3;
    const float m = g_rowmax[tile * 128 + tok];
    const float thr = m - 18.0f;
    float lsum = 0.0f;
    const float* Srow = g_S + ((size_t)tile * 128 + tok) * 2048;

    auto produce = [&](int s, int kc) {
        uint32_t A = G2_BASE(s);
        if (t == 0) {
            uint32_t full = sb + 16 + 8 * s;
            MBEXPECT(full, 65536u);
            bulk_g2s(sb + A + 16384, g_mtf2 + (size_t)kc * 65536, 65536u, full);
        }
        const float4* sp = (const float4*)(Srow + kc * 64 + q * 16);
        #pragma unroll
        for (int i = 0; i < 4; i++) {
            float4 sv = sp[i];
            float t4 = fmaxf(fmaxf(sv.x, sv.y), fmaxf(sv.z, sv.w));
            uint32_t off = A + SW128(tok * 128 + q * 32 + i * 8);
            if (t4 < thr) {
                *(ull*)(smem + off) = 0ull;
            } else {
                float p0 = __expf(sv.x - m), p1 = __expf(sv.y - m);
                float p2 = __expf(sv.z - m), p3 = __expf(sv.w - m);
                lsum += (p0 + p1) + (p2 + p3);
                __half2 h01 = __float22half2_rn(make_float2(p0, p1));
                __half2 h23 = __float22half2_rn(make_float2(p2, p3));
                uint2 u;
                u.x = *(uint32_t*)&h01;
                u.y = *(uint32_t*)&h23;
                *(uint2*)(smem + off) = u;
            }
        }
    };

    produce(0, 0);
    FENCE_ASYNC();
    __syncthreads();

    for (int kc = 0; kc < 32; kc++) {
        int s = kc & 1;
        if (t == 0) {
            MBWAIT(sb + 16 + 8 * s, (uint32_t)((kc >> 1) & 1));
            uint32_t base = G2_BASE(s);
            uint64_t a  = mk_desc(sb + base);
            uint64_t b0 = mk_desc(sb + base + 16384);
            uint64_t b1 = mk_desc(sb + base + 16384 + 32768);
            #pragma unroll
            for (int ks = 0; ks < 4; ks++)
                mma_f16_ss(tmem,       a + 2 * ks, b0 + 2 * ks, IDESC_F16,
                           (kc == 0 && ks == 0) ? 0u : 1u);
            #pragma unroll
            for (int ks = 0; ks < 4; ks++)
                mma_f16_ss(tmem + 256, a + 2 * ks, b1 + 2 * ks, IDESC_F16,
                           (kc == 0 && ks == 0) ? 0u : 1u);
            TCCOMMIT(sb + 32 + 8 * s);
        }
        if (kc < 31) {
            if (kc >= 1) {
                MBWAIT(sb + 32 + 8 * (s ^ 1), (uint32_t)(((kc - 1) >> 1) & 1));
            }
            produce(s ^ 1, kc + 1);
            FENCE_ASYNC();
        }
        __syncthreads();
    }
    MBWAIT(sb + 32, 1);
    MBWAIT(sb + 40, 1);

    lsum += __shfl_xor_sync(0xffffffffu, lsum, 1);
    lsum += __shfl_xor_sync(0xffffffffu, lsum, 2);
    if (q == 0) l_s[tok] = lsum;
    __syncthreads();
    TCFENCE_AFTER();

    if (wid < 4) {
        int tk = wid * 32 + lane;
        float rl = 1.0f / l_s[tk];
        float* St = (float*)(smem + 1024) + wid * (32 * 33);
        #pragma unroll 1
        for (int cc = 0; cc < 16; cc++) {
            uint32_t r[32];
            LDTM_X32(r, tmem + cc * 32);
            TCWAIT_LD();
            #pragma unroll
            for (int i = 0; i < 32; i++)
                St[i * 33 + lane] = __uint_as_float(r[i]) * rl;
            __syncwarp();
            float* dst = out + ((size_t)b * C_ + cc * 32 + lane) * N_ + n0 + wid * 32;
            const float* src = St + lane * 33;
            #pragma unroll
            for (int j = 0; j < 8; j++)
                ((float4*)dst)[j] = make_float4(src[4*j], src[4*j+1], src[4*j+2], src[4*j+3]);
            __syncwarp();
        }
    }
    __syncthreads();
    if (wid == 0) TCDEALLOC(tmem, 512);
}

// ================= launch =================
extern "C" void kernel_launch(void* const* d_in, const int* in_sizes, int n_in,
                              void* d_out, int out_size)
{
    const float* feat = (const float*)d_in[0];
    const float* mem  = (const float*)d_in[1];
    float* out        = (float*)d_out;
    (void)in_sizes; (void)n_in; (void)out_size;

    cudaFuncSetAttribute(k_gemm1, cudaFuncAttributeMaxDynamicSharedMemorySize, G1_SMEM);
    cudaFuncSetAttribute(k_gemm2, cudaFuncAttributeMaxDynamicSharedMemorySize, G2_SMEM);

    k_init_rowmax<<<256, 256>>>();
    k_prep_feat<<<dim3(C_ / 32, N_ / 32, B_), 256>>>(feat);
    k_prep_mem<<<(M_ * C_ / 2 + 255) / 256, 256>>>(mem);
    k_prep_memT<<<dim3(M_ / 32, C_ / 32), 256>>>(mem);
    k_gemm1<<<dim3(512, 8), 256, G1_SMEM>>>();   // cluster (2,1,1) via __cluster_dims__
    k_gemm2<<<512, 512, G2_SMEM>>>(out);
}